// round 1
// baseline (speedup 1.0000x reference)
#include <cuda_runtime.h>
#include <cuda_bf16.h>
#include <math.h>

// Problem constants (fixed by setup_inputs)
#define BATCH   16
#define LEN     262144
#define NFFT    1024
#define HOP     256
#define NT      1025          // frames
#define NF      513           // rfft bins
#define NFP     33            // freq patches (ceil(513/16))
#define NTP     65            // time patches (ceil(1025/16))
#define NP      2145          // patches per batch
#define KSEL    643           // int(2145*0.3)
#define MAGN    (BATCH*NT*NF) // 8,413,200 floats per signal

// Scratch (static device memory; no allocation allowed)
__device__ float g_mag[3ll * MAGN];       // [sig][b][t][f]
__device__ float g_kgs[BATCH * NP];
__device__ float g_pl [BATCH * NP];
__device__ float g_bsel[BATCH];
__device__ float g_bkgs[BATCH];
__device__ int   g_bpos[BATCH];

// ---------------------------------------------------------------------------
// Fully-unrolled register FFT-32 (DIT, bit-reversed input permute inlined,
// compile-time twiddles -> immediates)
// ---------------------------------------------------------------------------
__device__ __forceinline__ void fft32(float* xr, float* xi) {
    constexpr float C32[16] = {
        1.0f,          0.980785280f,  0.923879533f,  0.831469612f,
        0.707106781f,  0.555570233f,  0.382683432f,  0.195090322f,
        0.0f,         -0.195090322f, -0.382683432f, -0.555570233f,
       -0.707106781f, -0.831469612f, -0.923879533f, -0.980785280f };
    constexpr float S32[16] = {
        0.0f,          0.195090322f,  0.382683432f,  0.555570233f,
        0.707106781f,  0.831469612f,  0.923879533f,  0.980785280f,
        1.0f,          0.980785280f,  0.923879533f,  0.831469612f,
        0.707106781f,  0.555570233f,  0.382683432f,  0.195090322f };

    // bit-reverse permutation (5 bits)
#pragma unroll
    for (int j = 1; j < 32; j++) {
        int r = ((j & 1) << 4) | ((j & 2) << 2) | (j & 4) | ((j & 8) >> 2) | ((j & 16) >> 4);
        if (j < r) {
            float t;
            t = xr[j]; xr[j] = xr[r]; xr[r] = t;
            t = xi[j]; xi[j] = xi[r]; xi[r] = t;
        }
    }
#pragma unroll
    for (int s = 1; s <= 5; s++) {
        const int m = 1 << s, h = m >> 1;
#pragma unroll
        for (int g = 0; g < 32; g += (1 << s)) {
#pragma unroll
            for (int j = 0; j < h; j++) {
                const float wr =  C32[j << (5 - s)];
                const float wi = -S32[j << (5 - s)];
                const int a = g + j, c = g + j + h;
                float tr = wr * xr[c] - wi * xi[c];
                float ti = wr * xi[c] + wi * xr[c];
                xr[c] = xr[a] - tr; xi[c] = xi[a] - ti;
                xr[a] = xr[a] + tr; xi[a] = xi[a] + ti;
            }
        }
    }
}

// ---------------------------------------------------------------------------
// Kernel 1: STFT magnitudes. One warp = one complex-1024 FFT carrying TWO
// frames (two-for-one real trick). Four-step 32x32, pitch-33 shared (no bank
// conflicts), per-thread register FFT-32s.
// ---------------------------------------------------------------------------
__global__ __launch_bounds__(128) void stft_kernel(
    const float* __restrict__ xs, const float* __restrict__ xt,
    const float* __restrict__ xg)
{
    const int lane = threadIdx.x & 31;
    const int w    = threadIdx.x >> 5;
    const int pair = blockIdx.x * 4 + w;          // 24624 pairs total (exact)

    int sig = pair / (BATCH * 513);
    int rem = pair - sig * (BATCH * 513);
    int b   = rem / 513;
    int m   = rem - b * 513;

    const float* x = (sig == 0) ? xs : (sig == 1 ? xt : xg);
    x += (size_t)b * LEN;

    __shared__ float SRE[4][1056];
    __shared__ float SIM[4][1056];
    float* sre = SRE[w];
    float* sim = SIM[w];

    const int ta    = 2 * m;
    const bool hasb = (m < 512);                  // frame 2m+1 valid?
    const int base  = ta * HOP - 512;             // reflect-pad origin

    // stage input: z[n] = frameA[n] + i*frameB[n]
#pragma unroll
    for (int it = 0; it < 32; ++it) {
        int n  = it * 32 + lane;
        int sa = base + n;
        int ia = sa < 0 ? -sa : (sa >= LEN ? 2 * LEN - 2 - sa : sa);
        float va = x[ia];
        float vb = 0.f;
        if (hasb) {
            int sb = sa + HOP;
            int ib = sb < 0 ? -sb : (sb >= LEN ? 2 * LEN - 2 - sb : sb);
            vb = x[ib];
        }
        sre[it * 33 + lane] = va;
        sim[it * 33 + lane] = vb;
    }
    __syncwarp();

    float xr[32], xi[32];

    // Pass A: FFT32 over n2 (column n1=lane), then twiddle e^{-2pi i n1 k2/1024}
    {
        const int n1 = lane;
#pragma unroll
        for (int n2 = 0; n2 < 32; n2++) {
            xr[n2] = sre[n2 * 33 + n1];
            xi[n2] = sim[n2 * 33 + n1];
        }
        __syncwarp();
        fft32(xr, xi);
        float ss, sc;
        sincospif(-(float)n1 * (1.0f / 512.0f), &ss, &sc);   // e^{-2pi i n1/1024}
        float wr = 1.f, wi = 0.f;
#pragma unroll
        for (int k2 = 0; k2 < 32; k2++) {
            float ar = xr[k2], ai = xi[k2];
            sre[n1 * 33 + k2] = ar * wr - ai * wi;
            sim[n1 * 33 + k2] = ar * wi + ai * wr;
            float nwr = wr * sc - wi * ss;
            float nwi = wr * ss + wi * sc;
            wr = nwr; wi = nwi;
        }
    }
    __syncwarp();

    // Pass B: FFT32 over n1 (row k2=lane); result index k = k2 + 32*k1
    {
        const int k2 = lane;
#pragma unroll
        for (int n1 = 0; n1 < 32; n1++) {
            xr[n1] = sre[n1 * 33 + k2];
            xi[n1] = sim[n1 * 33 + k2];
        }
        __syncwarp();
        fft32(xr, xi);
#pragma unroll
        for (int k1 = 0; k1 < 32; k1++) {
            sre[k1 * 33 + k2] = xr[k1];
            sim[k1 * 33 + k2] = xi[k1];
        }
    }
    __syncwarp();

    // Unpack two real spectra + magnitudes
    float* out = g_mag + (size_t)sig * MAGN + ((size_t)b * NT + ta) * NF;
#pragma unroll
    for (int it = 0; it < 17; ++it) {
        int k = it * 32 + lane;
        if (k <= 512) {
            int kk = (1024 - k) & 1023;
            int a1 = (k  >> 5) * 33 + (k  & 31);
            int a2 = (kk >> 5) * 33 + (kk & 31);
            float zr = sre[a1], zi = sim[a1];
            float yr = sre[a2], yi = sim[a2];
            float mar = 0.5f * (zr + yr), mai = 0.5f * (zi - yi);
            float ma  = sqrtf(mar * mar + mai * mai);
            out[k] = fmaxf(ma, 1e-8f);
            if (hasb) {
                float mbr = 0.5f * (zi + yi), mbi = 0.5f * (yr - zr);
                float mb  = sqrtf(mbr * mbr + mbi * mbi);
                out[NF + k] = fmaxf(mb, 1e-8f);
            }
        }
    }
}

// ---------------------------------------------------------------------------
// Kernel 2: per-patch stats. One warp per patch (256 elems, 8 per lane).
// ---------------------------------------------------------------------------
__global__ __launch_bounds__(256) void patch_kernel() {
    const int lane = threadIdx.x & 31;
    const int wid  = threadIdx.x >> 5;
    const int gp   = blockIdx.x * 8 + wid;         // 34320 total (exact)
    const int b  = gp / NP;
    const int p  = gp - b * NP;
    const int fp = p / NTP;
    const int tp = p - fp * NTP;

    float sas = 0.f, sat = 0.f, ssq = 0.f;
#pragma unroll
    for (int j = 0; j < 8; j++) {
        int e  = j * 32 + lane;
        int df = e & 15, dt = e >> 4;
        int f  = fp * 16 + df;
        int t  = tp * 16 + dt;
        if (f < NF && t < NT) {
            size_t idx = ((size_t)b * NT + t) * NF + f;
            float s  = g_mag[idx];
            float tt = g_mag[(size_t)MAGN + idx];
            float g  = g_mag[2ll * MAGN + idx];
            sas += fabsf(s - g);
            sat += fabsf(tt - g);
            float d = s - tt;
            ssq += d * d;
        }
    }
#pragma unroll
    for (int o = 16; o; o >>= 1) {
        sas += __shfl_down_sync(0xffffffffu, sas, o);
        sat += __shfl_down_sync(0xffffffffu, sat, o);
        ssq += __shfl_down_sync(0xffffffffu, ssq, o);
    }
    if (lane == 0) {
        g_kgs[gp] = (sas - sat) * (1.0f / 256.0f);
        g_pl [gp] = ssq * (1.0f / 256.0f);
    }
}

// ---------------------------------------------------------------------------
// Kernel 3: per-batch top-k selection (exact, index-order tie-break) + stats
// ---------------------------------------------------------------------------
__device__ __forceinline__ int bredI(int v, int* scr) {
    const int tid = threadIdx.x;
#pragma unroll
    for (int o = 16; o; o >>= 1) v += __shfl_down_sync(0xffffffffu, v, o);
    __syncthreads();
    if ((tid & 31) == 0) scr[tid >> 5] = v;
    __syncthreads();
    int r = 0;
#pragma unroll
    for (int j = 0; j < 8; j++) r += scr[j];
    return r;
}
__device__ __forceinline__ float bredF(float v, float* scr) {
    const int tid = threadIdx.x;
#pragma unroll
    for (int o = 16; o; o >>= 1) v += __shfl_down_sync(0xffffffffu, v, o);
    __syncthreads();
    if ((tid & 31) == 0) scr[tid >> 5] = v;
    __syncthreads();
    float r = 0.f;
#pragma unroll
    for (int j = 0; j < 8; j++) r += scr[j];
    return r;
}

__global__ __launch_bounds__(256) void select_kernel() {
    const int b = blockIdx.x, tid = threadIdx.x;
    __shared__ unsigned su[NP];
    __shared__ float    spl[NP];
    __shared__ int      eqidx[NP];
    __shared__ int      iscr[8];
    __shared__ float    fscr[8];
    __shared__ int      eqc;

    float ksum = 0.f; int pcnt = 0;
    for (int i = tid; i < NP; i += 256) {
        float kv = g_kgs[b * NP + i];
        spl[i] = g_pl[b * NP + i];
        unsigned bits = __float_as_uint(kv);
        su[i] = (bits & 0x80000000u) ? ~bits : (bits | 0x80000000u); // order-preserving
        ksum += kv;
        pcnt += (kv > 0.f) ? 1 : 0;
    }
    if (tid == 0) eqc = 0;
    __syncthreads();

    ksum = bredF(ksum, fscr);
    pcnt = bredI(pcnt, iscr);

    // binary search for k-th largest key: max v with count(u >= v) >= KSEL
    unsigned long long lo = 0ull, hi = 0xFFFFFFFFull;
    while (lo < hi) {
        unsigned long long mid = lo + ((hi - lo + 1ull) >> 1);
        int c = 0;
        for (int i = tid; i < NP; i += 256)
            c += ((unsigned long long)su[i] >= mid) ? 1 : 0;
        c = bredI(c, iscr);
        if (c >= KSEL) lo = mid; else hi = mid - 1ull;
    }
    const unsigned v = (unsigned)lo;

    int cgt = 0; float ssel = 0.f;
    for (int i = tid; i < NP; i += 256) {
        unsigned u = su[i];
        if (u > v) { cgt++; ssel += spl[i]; }
        else if (u == v) { int pos = atomicAdd(&eqc, 1); eqidx[pos] = i; }
    }
    cgt  = bredI(cgt, iscr);
    ssel = bredF(ssel, fscr);
    __syncthreads();

    if (tid == 0) {
        int need = KSEL - cgt;         // >= 1 by construction
        int ce   = eqc;
        float extra = 0.f;
        if (need >= ce) {
            for (int j = 0; j < ce; j++) extra += spl[eqidx[j]];
        } else {
            // take 'need' equal-valued patches with SMALLEST indices (top_k tie rule)
            int last = -1;
            for (int t2 = 0; t2 < need; t2++) {
                int mn = 0x7fffffff;
                for (int j = 0; j < ce; j++) {
                    int ix = eqidx[j];
                    if (ix > last && ix < mn) mn = ix;
                }
                extra += spl[mn];
                last = mn;
            }
        }
        g_bsel[b] = (ssel + extra) * (1.0f / (float)KSEL);
        g_bkgs[b] = ksum;
        g_bpos[b] = pcnt;
    }
}

// ---------------------------------------------------------------------------
// Kernel 4: finalize the 4 scalars
// ---------------------------------------------------------------------------
__global__ void final_kernel(float* __restrict__ out) {
    const int t = threadIdx.x;
    float s  = (t < BATCH) ? g_bsel[t] : 0.f;
    float kg = (t < BATCH) ? g_bkgs[t] : 0.f;
    float pc = (t < BATCH) ? (float)g_bpos[t] : 0.f;
#pragma unroll
    for (int o = 16; o; o >>= 1) {
        s  += __shfl_down_sync(0xffffffffu, s,  o);
        kg += __shfl_down_sync(0xffffffffu, kg, o);
        pc += __shfl_down_sync(0xffffffffu, pc, o);
    }
    if (t == 0) {
        out[0] = s * (1.0f / (float)BATCH);                      // loss
        out[1] = (float)KSEL / (float)NP;                        // sel_ratio
        out[2] = kg / (float)(BATCH * NP);                       // kgs_mean
        out[3] = pc / (float)(BATCH * NP);                       // kgs_pos_ratio
    }
}

extern "C" void kernel_launch(void* const* d_in, const int* in_sizes, int n_in,
                              void* d_out, int out_size) {
    const float* xs = (const float*)d_in[0];
    const float* xt = (const float*)d_in[1];
    const float* xg = (const float*)d_in[2];
    float* out = (float*)d_out;

    stft_kernel<<<6156, 128>>>(xs, xt, xg);   // 24624 frame-pairs, 4 per block
    patch_kernel<<<4290, 256>>>();            // 34320 patches, 8 per block
    select_kernel<<<BATCH, 256>>>();
    final_kernel<<<1, 32>>>(out);
}